// round 16
// baseline (speedup 1.0000x reference)
#include <cuda_runtime.h>
#include <cuda_fp16.h>
#include <cstdint>

// ---------------- problem constants ----------------
#define NNODES 100000
#define NEDGES 1600000
#define DIN 128
#define H1 128
#define H2 64
#define NEG_SLOPE 0.2f

typedef unsigned long long ull;

// ---------------- device scratch (no allocations allowed) ----------------
static __device__ __align__(16) __half g_xh[(size_t)NNODES * 128]; // fp16 xl (gather source)
static __device__ __align__(16) float  g_h1[(size_t)NNODES * 128]; // layer-1 output (fp32)
static __device__ float    g_asrc[NNODES];
static __device__ float    g_adst[NNODES];
static __device__ float    g_loopsum[NNODES];
static __device__ float    g_loopattr[NNODES];
static __device__ int      g_cnt[NNODES];       // in-degree
static __device__ int      g_rowstart[NNODES];  // CSR row offsets (pre block-offset)
static __device__ int      g_fill[NNODES];      // fill cursors
static __device__ int      g_bsum[1024];        // scan block sums
// split-fp16 transposed weights: [n][k] n-major, k = 0..127
static __device__ __align__(16) __half g_wth1[128 * 128];
static __device__ __align__(16) __half g_wtl1[128 * 128];
static __device__ __align__(16) __half g_wth2[64 * 128];
static __device__ __align__(16) __half g_wtl2[64 * 128];

struct __align__(8) EdgeRec { int src; float ea; };
static __device__ EdgeRec  g_epack[NEDGES];     // CSR: (src, edge_attr) per slot
static __device__ float    g_c[2];              // dot(W_edge, att_edge) per layer
static __device__ int      g_is64;              // edge_index dtype flag

// ---------------- helpers ----------------
__device__ __forceinline__ float leaky(float x) {
    return x >= 0.f ? x : NEG_SLOPE * x;
}
__device__ __forceinline__ int clampi(int v, int lo, int hi) {
    return v < lo ? lo : (v > hi ? hi : v);
}
// 16B async copy global -> shared (LDGSTS)
__device__ __forceinline__ void cp_async16(uint32_t saddr, const void* gptr) {
    asm volatile("cp.async.cg.shared.global [%0], [%1], 16;" :: "r"(saddr), "l"(gptr));
}
__device__ __forceinline__ void cp_commit() {
    asm volatile("cp.async.commit_group;");
}
__device__ __forceinline__ void cp_wait0() {
    asm volatile("cp.async.wait_group 0;" ::: "memory");
}
// m16n8k16 fp16 MMA, fp32 accumulate
__device__ __forceinline__ void mma16816(float* c, const uint32_t* a, uint32_t b0, uint32_t b1) {
    asm volatile(
        "mma.sync.aligned.m16n8k16.row.col.f32.f16.f16.f32 "
        "{%0,%1,%2,%3}, {%4,%5,%6,%7}, {%8,%9}, {%0,%1,%2,%3};"
        : "+f"(c[0]), "+f"(c[1]), "+f"(c[2]), "+f"(c[3])
        : "r"(a[0]), "r"(a[1]), "r"(a[2]), "r"(a[3]), "r"(b0), "r"(b1));
}
// split a float2 into hi/lo half2 (packed as uint32)
__device__ __forceinline__ void split2(float2 f, uint32_t& h, uint32_t& l) {
    __half h0 = __float2half_rn(f.x), h1 = __float2half_rn(f.y);
    __half l0 = __float2half_rn(f.x - __half2float(h0));
    __half l1 = __float2half_rn(f.y - __half2float(h1));
    __half2 hh = __halves2half2(h0, h1);
    __half2 ll = __halves2half2(l0, l1);
    h = *(uint32_t*)&hh;
    l = *(uint32_t*)&ll;
}

// ---------------- fused prep: zero / dtype / c-dots / W split-transpose ----------------
__global__ void prep_misc(const int* __restrict__ w,
                          const float* __restrict__ We1, const float* __restrict__ ae1,
                          const float* __restrict__ We2, const float* __restrict__ ae2,
                          const float* __restrict__ W1, const float* __restrict__ W2,
                          int n, int nbN) {
    int b = blockIdx.x;
    if (b < nbN) {
        int i = b * blockDim.x + threadIdx.x;
        if (i < n) { g_cnt[i] = 0; g_fill[i] = 0; g_loopsum[i] = 0.f; }
        return;
    }
    if (b == nbN) {
        if (threadIdx.x < 32) {
            int any = 0;
            for (int k = threadIdx.x; k < 512; k += 32) any |= w[2 * k + 1];
            #pragma unroll
            for (int o = 16; o; o >>= 1) any |= __shfl_down_sync(0xFFFFFFFFu, any, o);
            if (threadIdx.x == 0) g_is64 = (any == 0) ? 1 : 0;
        }
        return;
    }
    if (b == nbN + 1) {
        __shared__ float s1[128], s2[128];
        int t = threadIdx.x;
        if (t < 128) {
            s1[t] = We1[t] * ae1[t];
            s2[t] = (t < 64) ? We2[t] * ae2[t] : 0.f;
        }
        __syncthreads();
        for (int o = 64; o; o >>= 1) {
            if (t < o && t < 128) { s1[t] += s1[t + o]; s2[t] += s2[t + o]; }
            __syncthreads();
        }
        if (t == 0) { g_c[0] = s1[0]; g_c[1] = s2[0]; }
        return;
    }
    // W split + transpose: 96 blocks x 256 threads = 24576 = 128*128 + 128*64
    int i = (b - nbN - 2) * blockDim.x + threadIdx.x;
    if (i < 128 * 128) {
        int k = i >> 7, nn = i & 127;           // W1[k][n]
        float v = W1[i];
        __half h = __float2half_rn(v);
        __half l = __float2half_rn(v - __half2float(h));
        g_wth1[nn * 128 + k] = h;
        g_wtl1[nn * 128 + k] = l;
    } else if (i < 128 * 128 + 128 * 64) {
        int i2 = i - 128 * 128;
        int k = i2 >> 6, nn = i2 & 63;          // W2[k][n]
        float v = W2[i2];
        __half h = __float2half_rn(v);
        __half l = __float2half_rn(v - __half2float(h));
        g_wth2[nn * 128 + k] = h;
        g_wtl2[nn * 128 + k] = l;
    }
}

// ---------------- edge decode ----------------
__device__ __forceinline__ void decode_edge(const int* __restrict__ w, int e, int E, int N,
                                            int& s, int& d) {
    if (g_is64) {
        const long long* w64 = (const long long*)w;
        s = (int)w64[e];
        d = (int)w64[(size_t)E + e];
    } else {
        s = w[e];
        d = w[(size_t)E + e];
    }
    s = clampi(s, 0, N - 1);
    d = clampi(d, 0, N - 1);
}

// ---------------- degree histogram + loop attr sum (dst only) ----------------
__global__ void conv_hist(const int* __restrict__ w, const float* __restrict__ ea, int E, int N) {
    int e = blockIdx.x * blockDim.x + threadIdx.x;
    if (e >= E) return;
    int d;
    if (g_is64) d = (int)((const long long*)w)[(size_t)E + e];
    else        d = w[(size_t)E + e];
    d = clampi(d, 0, N - 1);
    atomicAdd(&g_cnt[d], 1);
    atomicAdd(&g_loopsum[d], ea[e]);
}

// ---------------- scan1 (+ fused loop_attr) / scan2 ----------------
__global__ void scan1(int n) {
    __shared__ int s[256];
    int t = threadIdx.x;
    int i = blockIdx.x * 256 + t;
    int v = (i < n) ? g_cnt[i] : 0;
    if (i < n) g_loopattr[i] = g_loopsum[i] / fmaxf((float)v, 1.f);
    s[t] = v;
    __syncthreads();
    #pragma unroll
    for (int o = 1; o < 256; o <<= 1) {
        int y = (t >= o) ? s[t - o] : 0;
        __syncthreads();
        s[t] += y;
        __syncthreads();
    }
    if (i < n) g_rowstart[i] = s[t] - v;
    if (t == 255) g_bsum[blockIdx.x] = s[255];
}
__global__ void scan2(int nb) {
    __shared__ int s[1024];
    int t = threadIdx.x;
    int v = (t < nb) ? g_bsum[t] : 0;
    s[t] = v;
    __syncthreads();
    #pragma unroll
    for (int o = 1; o < 1024; o <<= 1) {
        int y = (t >= o) ? s[t - o] : 0;
        __syncthreads();
        s[t] += y;
        __syncthreads();
    }
    if (t < nb) g_bsum[t] = s[t] - v;
}

// ---------------- CSR fill ----------------
__global__ void csr_fill(const int* __restrict__ w, const float* __restrict__ ea, int E, int N) {
    int e = blockIdx.x * blockDim.x + threadIdx.x;
    if (e >= E) return;
    int s, d;
    decode_edge(w, e, E, N, s, d);
    int pos = g_rowstart[d] + g_bsum[d >> 8] + atomicAdd(&g_fill[d], 1);
    EdgeRec r;
    r.src = s;
    r.ea = ea[e];
    g_epack[pos] = r;
}

// ---------------- persistent tensor-core GEMM (split-fp16, ~fp32 accurate) ----------------
// R13 proven config: 128 threads (4 warps), BM=64 rows/tile; W staged once;
// A double-buffered cp.async. D = Ah*Wh + Al*Wh + Ah*Wl.
template <int F, bool A_IS_H1>
__global__ __launch_bounds__(128) void gemm_mma(const float* __restrict__ Ain,
                                                const __half* __restrict__ Wth,
                                                const __half* __restrict__ Wtl,
                                                const float* __restrict__ atts,
                                                const float* __restrict__ attd,
                                                int N, int numTiles) {
    const float* A = A_IS_H1 ? (const float*)g_h1 : Ain;
    constexpr int KP = 136;                       // padded k
    constexpr int NT = F / 8;                     // n-tiles per warp: 16 / 8
    extern __shared__ __align__(16) char smem_raw[];
    __half* sWh = (__half*)smem_raw;              // [F][KP] n-major
    __half* sWl = sWh + F * KP;
    float*  sA  = (float*)(sWl + F * KP);         // [2][64][KP] fp32

    const int tid = threadIdx.x;
    const int warp = tid >> 5;
    const int lane = tid & 31;
    const int g = lane >> 2, t = lane & 3;
    const int arow = warp * 16;
    const uint32_t sa_base = (uint32_t)__cvta_generic_to_shared(sA);

    // ---- stage W once (hi/lo, cp.async) ----
    {
        uint32_t swh = (uint32_t)__cvta_generic_to_shared(sWh);
        uint32_t swl = (uint32_t)__cvta_generic_to_shared(sWl);
        for (int q = tid; q < F * 16; q += 128) {   // 16B chunks: 8 halves
            int n = q >> 4, c = q & 15;
            cp_async16(swh + n * (KP * 2) + c * 16, Wth + n * 128 + c * 8);
            cp_async16(swl + n * (KP * 2) + c * 16, Wtl + n * 128 + c * 8);
        }
    }

    #define STAGE_A(tile, bufi) do {                                           \
        int _row0 = (tile) * 64;                                               \
        uint32_t _sa = sa_base + (uint32_t)(bufi) * 64 * KP * 4;               \
        _Pragma("unroll")                                                      \
        for (int _q = 0; _q < 16; _q++) {                                      \
            int _f4 = tid + _q * 128;                                          \
            int _r = _f4 >> 5, _c = _f4 & 31;                                  \
            int _gr = _row0 + _r;                                              \
            if (_gr >= N) _gr = N - 1;                                         \
            cp_async16(_sa + (uint32_t)(_r * KP + _c * 4) * 4,                 \
                       A + (size_t)_gr * 128 + _c * 4);                        \
        }                                                                      \
        cp_commit();                                                           \
    } while (0)

    int buf = 0;
    bool first = true;
    for (int tile = blockIdx.x; tile < numTiles; tile += gridDim.x) {
        if (first) {
            STAGE_A(tile, 0);         // commits W + A0 together
            cp_wait0();
            __syncthreads();
            first = false;
        }
        int nextTile = tile + gridDim.x;
        if (nextTile < numTiles) STAGE_A(nextTile, buf ^ 1);

        const int row0 = tile * 64;
        const float* sAb = sA + buf * 64 * KP;

        float acc[NT][4];
        #pragma unroll
        for (int j = 0; j < NT; j++)
            #pragma unroll
            for (int q = 0; q < 4; q++) acc[j][q] = 0.f;

        #pragma unroll
        for (int kc = 0; kc < 8; kc++) {
            const int kb = kc * 16;
            uint32_t ah[4], al[4];
            {
                const float* pa = sAb + (arow + g) * KP + kb + 2 * t;
                float2 f0 = *(const float2*)pa;
                float2 f1 = *(const float2*)(pa + 8 * KP);
                float2 f2 = *(const float2*)(pa + 8);
                float2 f3 = *(const float2*)(pa + 8 * KP + 8);
                split2(f0, ah[0], al[0]);
                split2(f1, ah[1], al[1]);
                split2(f2, ah[2], al[2]);
                split2(f3, ah[3], al[3]);
            }
            #pragma unroll
            for (int j = 0; j < NT; j++) {
                const __half* pb = sWh + (j * 8 + g) * KP + kb + 2 * t;
                uint32_t bh0 = *(const uint32_t*)pb;
                uint32_t bh1 = *(const uint32_t*)(pb + 8);
                const __half* pc = sWl + (j * 8 + g) * KP + kb + 2 * t;
                uint32_t bl0 = *(const uint32_t*)pc;
                uint32_t bl1 = *(const uint32_t*)(pc + 8);
                mma16816(acc[j], ah, bh0, bh1);
                mma16816(acc[j], al, bh0, bh1);
                mma16816(acc[j], ah, bl0, bl1);
            }
        }

        // ---- epilogue: att dots + fp16 feature store ----
        int r0 = row0 + arow + g;
        int r1 = r0 + 8;
        float s0 = 0.f, d0 = 0.f, s1 = 0.f, d1 = 0.f;
        #pragma unroll
        for (int j = 0; j < NT; j++) {
            int c0 = j * 8 + 2 * t;
            float as0 = __ldg(&atts[c0]), as1 = __ldg(&atts[c0 + 1]);
            float ad0 = __ldg(&attd[c0]), ad1 = __ldg(&attd[c0 + 1]);
            s0 += acc[j][0] * as0 + acc[j][1] * as1;
            d0 += acc[j][0] * ad0 + acc[j][1] * ad1;
            s1 += acc[j][2] * as0 + acc[j][3] * as1;
            d1 += acc[j][2] * ad0 + acc[j][3] * ad1;
            if (r0 < N)
                *(__half2*)&g_xh[(size_t)r0 * F + c0] = __floats2half2_rn(acc[j][0], acc[j][1]);
            if (r1 < N)
                *(__half2*)&g_xh[(size_t)r1 * F + c0] = __floats2half2_rn(acc[j][2], acc[j][3]);
        }
        #pragma unroll
        for (int o = 1; o <= 2; o <<= 1) {
            s0 += __shfl_xor_sync(0xFFFFFFFFu, s0, o);
            d0 += __shfl_xor_sync(0xFFFFFFFFu, d0, o);
            s1 += __shfl_xor_sync(0xFFFFFFFFu, s1, o);
            d1 += __shfl_xor_sync(0xFFFFFFFFu, d1, o);
        }
        if (t == 0) {
            if (r0 < N) { g_asrc[r0] = s0; g_adst[r0] = d0; }
            if (r1 < N) { g_asrc[r1] = s1; g_adst[r1] = d1; }
        }

        if (nextTile < numTiles) {
            cp_wait0();
            __syncthreads();
            buf ^= 1;
        }
    }
    #undef STAGE_A
}

// ---------------- feature load helper (fp16 -> fp32) ----------------
template <int VE>
__device__ __forceinline__ void load_feat(float* v, const __half* p) {
    if (VE == 4) {
        uint2 u = *(const uint2*)p;
        float2 f0 = __half22float2(*(const __half2*)&u.x);
        float2 f1 = __half22float2(*(const __half2*)&u.y);
        v[0] = f0.x; v[1] = f0.y; v[2] = f1.x; v[3] = f1.y;
    } else {
        uint32_t u = *(const uint32_t*)p;
        float2 f0 = __half22float2(*(const __half2*)&u);
        v[0] = f0.x; v[1] = f0.y;
    }
}

// ---------------- fused GAT: direct softmax (no max shift), record prefetch ----------------
// Softmax is shift-invariant; logits are O(10) here (glorot weights, unit-variance
// features) vs fp32 exp overflow at 88 -> direct exp is safe and kills the serial
// online-max dependency chain. EdgeRecs prefetched one group ahead.
template <int F, bool OUT_IS_H1>
__global__ void fused_gat(const float* __restrict__ bias, const float* __restrict__ prelu_a,
                          float* __restrict__ outp, int N, int layer) {
    int w = (blockIdx.x * blockDim.x + threadIdx.x) >> 5;
    int lane = threadIdx.x & 31;
    if (w >= N) return;
    float* out = OUT_IS_H1 ? (float*)g_h1 : outp;
    constexpr int VE = F / 32;
    const float c = g_c[layer];
    const float adst = g_adst[w];

    // self-loop
    float pself = __expf(leaky(g_asrc[w] + adst + c * g_loopattr[w]));
    float den = pself;
    float acc[VE];
    load_feat<VE>(acc, g_xh + (size_t)w * F + lane * VE);
    #pragma unroll
    for (int q = 0; q < VE; q++) acc[q] *= pself;

    const int beg = g_rowstart[w] + g_bsum[w >> 8];
    const int cnt = g_cnt[w];

    EdgeRec er0, er1, er2, er3;
    if (cnt >= 4) {
        er0 = g_epack[beg];
        er1 = g_epack[beg + 1];
        er2 = g_epack[beg + 2];
        er3 = g_epack[beg + 3];
    }
    int j = 0;
    for (; j + 4 <= cnt; j += 4) {
        // loads for current group (addresses ready from prefetch)
        float a0 = g_asrc[er0.src], a1 = g_asrc[er1.src];
        float a2 = g_asrc[er2.src], a3 = g_asrc[er3.src];
        float v0[VE], v1[VE], v2[VE], v3[VE];
        load_feat<VE>(v0, g_xh + (size_t)er0.src * F + lane * VE);
        load_feat<VE>(v1, g_xh + (size_t)er1.src * F + lane * VE);
        load_feat<VE>(v2, g_xh + (size_t)er2.src * F + lane * VE);
        load_feat<VE>(v3, g_xh + (size_t)er3.src * F + lane * VE);
        // prefetch next group records (overlaps current round trip)
        EdgeRec n0, n1, n2, n3;
        bool more = (j + 8 <= cnt);
        if (more) {
            n0 = g_epack[beg + j + 4];
            n1 = g_epack[beg + j + 5];
            n2 = g_epack[beg + j + 6];
            n3 = g_epack[beg + j + 7];
        }
        // independent exp + accumulate (no serial chain)
        float p0 = __expf(leaky(a0 + adst + c * er0.ea));
        float p1 = __expf(leaky(a1 + adst + c * er1.ea));
        float p2 = __expf(leaky(a2 + adst + c * er2.ea));
        float p3 = __expf(leaky(a3 + adst + c * er3.ea));
        den += (p0 + p1) + (p2 + p3);
        #pragma unroll
        for (int q = 0; q < VE; q++)
            acc[q] += (p0 * v0[q] + p1 * v1[q]) + (p2 * v2[q] + p3 * v3[q]);
        if (more) { er0 = n0; er1 = n1; er2 = n2; er3 = n3; }
    }
    for (; j < cnt; j++) {
        EdgeRec er = g_epack[beg + j];
        float p = __expf(leaky(g_asrc[er.src] + adst + c * er.ea));
        float v[VE];
        load_feat<VE>(v, g_xh + (size_t)er.src * F + lane * VE);
        den += p;
        #pragma unroll
        for (int q = 0; q < VE; q++) acc[q] += p * v[q];
    }

    float inv = 1.f / den;
    float a = *prelu_a;
    #pragma unroll
    for (int q = 0; q < VE; q++) {
        float o = acc[q] * inv + bias[lane * VE + q];
        out[(size_t)w * F + lane * VE + q] = o > 0.f ? o : a * o;
    }
}

template <typename T>
static T* sym_addr(const void* sym) {
    void* p = nullptr;
    cudaGetSymbolAddress(&p, sym);
    return (T*)p;
}

extern "C" void kernel_launch(void* const* d_in, const int* in_sizes, int n_in,
                              void* d_out, int out_size) {
    const float*      x    = (const float*)d_in[0];
    const int*        eiw  = (const int*)d_in[1];
    const float*      ea   = (const float*)d_in[2];
    const float*      W1   = (const float*)d_in[3];
    const float*      as1  = (const float*)d_in[4];
    const float*      ad1  = (const float*)d_in[5];
    const float*      We1  = (const float*)d_in[6];
    const float*      ae1  = (const float*)d_in[7];
    const float*      b1   = (const float*)d_in[8];
    const float*      W2   = (const float*)d_in[9];
    const float*      as2  = (const float*)d_in[10];
    const float*      ad2  = (const float*)d_in[11];
    const float*      We2  = (const float*)d_in[12];
    const float*      ae2  = (const float*)d_in[13];
    const float*      b2   = (const float*)d_in[14];
    const float*      pa   = (const float*)d_in[15];
    float*            out  = (float*)d_out;

    const int N = in_sizes[0] / DIN;
    const int E = in_sizes[1] / 2;

    const int TB = 256;
    int nb_N   = (N + TB - 1) / TB;
    int nb_E   = (E + TB - 1) / TB;
    int nb_att = ((N * 32) + TB - 1) / TB;
    int numTiles = (N + 63) / 64;            // BM=64

    const __half* wth1 = sym_addr<__half>(&g_wth1);
    const __half* wtl1 = sym_addr<__half>(&g_wtl1);
    const __half* wth2 = sym_addr<__half>(&g_wth2);
    const __half* wtl2 = sym_addr<__half>(&g_wtl2);

    // smem: W hi/lo (F*136*2*2) + A double buffer (2*64*136*4)
    constexpr int SM1 = 2 * H1 * 136 * 2 + 2 * 64 * 136 * 4;   // 139264
    constexpr int SM2 = 2 * H2 * 136 * 2 + 2 * 64 * 136 * 4;   // 104448
    cudaFuncSetAttribute(gemm_mma<H1, false>, cudaFuncAttributeMaxDynamicSharedMemorySize, SM1);
    cudaFuncSetAttribute(gemm_mma<H2, true>,  cudaFuncAttributeMaxDynamicSharedMemorySize, SM2);
    const int G1 = 148;    // 1 block/SM
    const int G2 = 296;    // 2 blocks/SM

    // gemm1 at my-launch #4 (ncu -s 5 profile target)
    prep_misc<<<nb_N + 2 + 96, TB>>>(eiw, We1, ae1, We2, ae2, W1, W2, N, nb_N);  // 1
    conv_hist<<<nb_E, TB>>>(eiw, ea, E, N);                                      // 2
    scan1<<<nb_N, 256>>>(N);                                                     // 3
    gemm_mma<H1, false><<<G1, 128, SM1>>>(x, wth1, wtl1, as1, ad1, N, numTiles); // 4
    scan2<<<1, 1024>>>(nb_N);                                                    // 5
    csr_fill<<<nb_E, TB>>>(eiw, ea, E, N);                                       // 6
    fused_gat<H1, true><<<nb_att, TB>>>(b1, pa, out, N, 0);                      // 7
    gemm_mma<H2, true><<<G2, 128, SM2>>>(nullptr, wth2, wtl2, as2, ad2, N, numTiles); // 8
    fused_gat<H2, false><<<nb_att, TB>>>(b2, pa, out, N, 1);                     // 9
}

// round 17
// speedup vs baseline: 1.0949x; 1.0949x over previous
#include <cuda_runtime.h>
#include <cuda_fp16.h>
#include <cstdint>

// ---------------- problem constants ----------------
#define NNODES 100000
#define NEDGES 1600000
#define DIN 128
#define H1 128
#define H2 64
#define NEG_SLOPE 0.2f

typedef unsigned long long ull;

// ---------------- device scratch (no allocations allowed) ----------------
static __device__ __align__(16) __half g_xh[(size_t)NNODES * 128];  // fp16 xl (gather source)
static __device__ __align__(16) __half g_h1h[(size_t)NNODES * 128]; // layer-1 output (fp16)
static __device__ float    g_asrc[NNODES];
static __device__ float    g_adst[NNODES];
static __device__ float    g_loopsum[NNODES];
static __device__ float    g_loopattr[NNODES];
static __device__ int      g_cnt[NNODES];       // in-degree
static __device__ int      g_rowstart[NNODES];  // CSR row offsets (pre block-offset)
static __device__ int      g_fill[NNODES];      // fill cursors
static __device__ int      g_bsum[1024];        // scan block sums
// split-fp16 transposed weights: [n][k] n-major, k = 0..127
static __device__ __align__(16) __half g_wth1[128 * 128];
static __device__ __align__(16) __half g_wtl1[128 * 128];
static __device__ __align__(16) __half g_wth2[64 * 128];
static __device__ __align__(16) __half g_wtl2[64 * 128];

struct __align__(8) EdgeRec { int src; float ea; };
static __device__ EdgeRec  g_epack[NEDGES];     // CSR: (src, edge_attr) per slot
static __device__ float    g_c[2];              // dot(W_edge, att_edge) per layer
static __device__ int      g_is64;              // edge_index dtype flag

// ---------------- helpers ----------------
__device__ __forceinline__ float leaky(float x) {
    return x >= 0.f ? x : NEG_SLOPE * x;
}
__device__ __forceinline__ int clampi(int v, int lo, int hi) {
    return v < lo ? lo : (v > hi ? hi : v);
}
__device__ __forceinline__ void cp_async16(uint32_t saddr, const void* gptr) {
    asm volatile("cp.async.cg.shared.global [%0], [%1], 16;" :: "r"(saddr), "l"(gptr));
}
__device__ __forceinline__ void cp_commit() {
    asm volatile("cp.async.commit_group;");
}
__device__ __forceinline__ void cp_wait0() {
    asm volatile("cp.async.wait_group 0;" ::: "memory");
}
__device__ __forceinline__ void mma16816(float* c, const uint32_t* a, uint32_t b0, uint32_t b1) {
    asm volatile(
        "mma.sync.aligned.m16n8k16.row.col.f32.f16.f16.f32 "
        "{%0,%1,%2,%3}, {%4,%5,%6,%7}, {%8,%9}, {%0,%1,%2,%3};"
        : "+f"(c[0]), "+f"(c[1]), "+f"(c[2]), "+f"(c[3])
        : "r"(a[0]), "r"(a[1]), "r"(a[2]), "r"(a[3]), "r"(b0), "r"(b1));
}
__device__ __forceinline__ void split2(float2 f, uint32_t& h, uint32_t& l) {
    __half h0 = __float2half_rn(f.x), h1 = __float2half_rn(f.y);
    __half l0 = __float2half_rn(f.x - __half2float(h0));
    __half l1 = __float2half_rn(f.y - __half2float(h1));
    __half2 hh = __halves2half2(h0, h1);
    __half2 ll = __halves2half2(l0, l1);
    h = *(uint32_t*)&hh;
    l = *(uint32_t*)&ll;
}

// ---------------- fused prep: zero / dtype / c-dots / W split-transpose ----------------
__global__ void prep_misc(const int* __restrict__ w,
                          const float* __restrict__ We1, const float* __restrict__ ae1,
                          const float* __restrict__ We2, const float* __restrict__ ae2,
                          const float* __restrict__ W1, const float* __restrict__ W2,
                          int n, int nbN) {
    int b = blockIdx.x;
    if (b < nbN) {
        int i = b * blockDim.x + threadIdx.x;
        if (i < n) { g_cnt[i] = 0; g_fill[i] = 0; g_loopsum[i] = 0.f; }
        return;
    }
    if (b == nbN) {
        if (threadIdx.x < 32) {
            int any = 0;
            for (int k = threadIdx.x; k < 512; k += 32) any |= w[2 * k + 1];
            #pragma unroll
            for (int o = 16; o; o >>= 1) any |= __shfl_down_sync(0xFFFFFFFFu, any, o);
            if (threadIdx.x == 0) g_is64 = (any == 0) ? 1 : 0;
        }
        return;
    }
    if (b == nbN + 1) {
        __shared__ float s1[128], s2[128];
        int t = threadIdx.x;
        if (t < 128) {
            s1[t] = We1[t] * ae1[t];
            s2[t] = (t < 64) ? We2[t] * ae2[t] : 0.f;
        }
        __syncthreads();
        for (int o = 64; o; o >>= 1) {
            if (t < o && t < 128) { s1[t] += s1[t + o]; s2[t] += s2[t + o]; }
            __syncthreads();
        }
        if (t == 0) { g_c[0] = s1[0]; g_c[1] = s2[0]; }
        return;
    }
    // W split + transpose: 96 blocks x 256 threads = 24576 = 128*128 + 128*64
    int i = (b - nbN - 2) * blockDim.x + threadIdx.x;
    if (i < 128 * 128) {
        int k = i >> 7, nn = i & 127;           // W1[k][n]
        float v = W1[i];
        __half h = __float2half_rn(v);
        __half l = __float2half_rn(v - __half2float(h));
        g_wth1[nn * 128 + k] = h;
        g_wtl1[nn * 128 + k] = l;
    } else if (i < 128 * 128 + 128 * 64) {
        int i2 = i - 128 * 128;
        int k = i2 >> 6, nn = i2 & 63;          // W2[k][n]
        float v = W2[i2];
        __half h = __float2half_rn(v);
        __half l = __float2half_rn(v - __half2float(h));
        g_wth2[nn * 128 + k] = h;
        g_wtl2[nn * 128 + k] = l;
    }
}

// ---------------- edge decode ----------------
__device__ __forceinline__ void decode_edge(const int* __restrict__ w, int e, int E, int N,
                                            int& s, int& d) {
    if (g_is64) {
        const long long* w64 = (const long long*)w;
        s = (int)w64[e];
        d = (int)w64[(size_t)E + e];
    } else {
        s = w[e];
        d = w[(size_t)E + e];
    }
    s = clampi(s, 0, N - 1);
    d = clampi(d, 0, N - 1);
}

// ---------------- degree histogram + loop attr sum ----------------
__global__ void conv_hist(const int* __restrict__ w, const float* __restrict__ ea, int E, int N) {
    int e = blockIdx.x * blockDim.x + threadIdx.x;
    if (e >= E) return;
    int s, d;
    decode_edge(w, e, E, N, s, d);
    atomicAdd(&g_cnt[d], 1);
    atomicAdd(&g_loopsum[d], ea[e]);
}

// ---------------- scan1 (+ fused loop_attr) / scan2 ----------------
__global__ void scan1(int n) {
    __shared__ int s[256];
    int t = threadIdx.x;
    int i = blockIdx.x * 256 + t;
    int v = (i < n) ? g_cnt[i] : 0;
    if (i < n) g_loopattr[i] = g_loopsum[i] / fmaxf((float)v, 1.f);
    s[t] = v;
    __syncthreads();
    #pragma unroll
    for (int o = 1; o < 256; o <<= 1) {
        int y = (t >= o) ? s[t - o] : 0;
        __syncthreads();
        s[t] += y;
        __syncthreads();
    }
    if (i < n) g_rowstart[i] = s[t] - v;
    if (t == 255) g_bsum[blockIdx.x] = s[255];
}
__global__ void scan2(int nb) {
    __shared__ int s[1024];
    int t = threadIdx.x;
    int v = (t < nb) ? g_bsum[t] : 0;
    s[t] = v;
    __syncthreads();
    #pragma unroll
    for (int o = 1; o < 1024; o <<= 1) {
        int y = (t >= o) ? s[t - o] : 0;
        __syncthreads();
        s[t] += y;
        __syncthreads();
    }
    if (t < nb) g_bsum[t] = s[t] - v;
}

// ---------------- CSR fill ----------------
__global__ void csr_fill(const int* __restrict__ w, const float* __restrict__ ea, int E, int N) {
    int e = blockIdx.x * blockDim.x + threadIdx.x;
    if (e >= E) return;
    int s, d;
    decode_edge(w, e, E, N, s, d);
    int pos = g_rowstart[d] + g_bsum[d >> 8] + atomicAdd(&g_fill[d], 1);
    EdgeRec r;
    r.src = s;
    r.ea = ea[e];
    g_epack[pos] = r;
}

// ---------------- GEMM1: persistent, single A buffer, 2 blocks/SM ----------------
// 128 threads (4 warps), BM=64. A fp32 from x, split to hi/lo in registers.
// D = Ah*Wh + Al*Wh + Ah*Wl.
__global__ __launch_bounds__(128) void gemm_mma1(const float* __restrict__ A,
                                                 const __half* __restrict__ Wth,
                                                 const __half* __restrict__ Wtl,
                                                 const float* __restrict__ atts,
                                                 const float* __restrict__ attd,
                                                 int N, int numTiles) {
    constexpr int F = 128, KP = 136, NT = 16;
    extern __shared__ __align__(16) char smem_raw[];
    __half* sWh = (__half*)smem_raw;              // [F][KP]
    __half* sWl = sWh + F * KP;
    float*  sA  = (float*)(sWl + F * KP);         // [64][KP] fp32 (single buffer)

    const int tid = threadIdx.x;
    const int warp = tid >> 5;
    const int lane = tid & 31;
    const int g = lane >> 2, t = lane & 3;
    const int arow = warp * 16;
    const uint32_t sa = (uint32_t)__cvta_generic_to_shared(sA);

    // stage W once (joins first commit group)
    {
        uint32_t swh = (uint32_t)__cvta_generic_to_shared(sWh);
        uint32_t swl = (uint32_t)__cvta_generic_to_shared(sWl);
        for (int q = tid; q < F * 16; q += 128) {
            int n = q >> 4, c = q & 15;
            cp_async16(swh + n * (KP * 2) + c * 16, Wth + n * 128 + c * 8);
            cp_async16(swl + n * (KP * 2) + c * 16, Wtl + n * 128 + c * 8);
        }
    }

    bool first = true;
    for (int tile = blockIdx.x; tile < numTiles; tile += gridDim.x) {
        if (!first) __syncthreads();       // WAR: previous compute done before overwrite
        // stage A (16 chunks/thread)
        {
            int row0 = tile * 64;
            #pragma unroll
            for (int q = 0; q < 16; q++) {
                int f4 = tid + q * 128;
                int r = f4 >> 5, c = f4 & 31;
                int gr = row0 + r;
                if (gr >= N) gr = N - 1;
                cp_async16(sa + (uint32_t)(r * KP + c * 4) * 4, A + (size_t)gr * 128 + c * 4);
            }
            cp_commit();
        }
        cp_wait0();
        __syncthreads();
        first = false;

        const int row0 = tile * 64;
        float acc[NT][4];
        #pragma unroll
        for (int j = 0; j < NT; j++)
            #pragma unroll
            for (int q = 0; q < 4; q++) acc[j][q] = 0.f;

        #pragma unroll
        for (int kc = 0; kc < 8; kc++) {
            const int kb = kc * 16;
            uint32_t ah[4], al[4];
            {
                const float* pa = sA + (arow + g) * KP + kb + 2 * t;
                float2 f0 = *(const float2*)pa;
                float2 f1 = *(const float2*)(pa + 8 * KP);
                float2 f2 = *(const float2*)(pa + 8);
                float2 f3 = *(const float2*)(pa + 8 * KP + 8);
                split2(f0, ah[0], al[0]);
                split2(f1, ah[1], al[1]);
                split2(f2, ah[2], al[2]);
                split2(f3, ah[3], al[3]);
            }
            #pragma unroll
            for (int j = 0; j < NT; j++) {
                const __half* pb = sWh + (j * 8 + g) * KP + kb + 2 * t;
                uint32_t bh0 = *(const uint32_t*)pb;
                uint32_t bh1 = *(const uint32_t*)(pb + 8);
                const __half* pc = sWl + (j * 8 + g) * KP + kb + 2 * t;
                uint32_t bl0 = *(const uint32_t*)pc;
                uint32_t bl1 = *(const uint32_t*)(pc + 8);
                mma16816(acc[j], ah, bh0, bh1);
                mma16816(acc[j], al, bh0, bh1);
                mma16816(acc[j], ah, bl0, bl1);
            }
        }

        // epilogue: att dots + fp16 feature store
        int r0 = row0 + arow + g;
        int r1 = r0 + 8;
        float s0 = 0.f, d0 = 0.f, s1 = 0.f, d1 = 0.f;
        #pragma unroll
        for (int j = 0; j < NT; j++) {
            int c0 = j * 8 + 2 * t;
            float as0 = __ldg(&atts[c0]), as1 = __ldg(&atts[c0 + 1]);
            float ad0 = __ldg(&attd[c0]), ad1 = __ldg(&attd[c0 + 1]);
            s0 += acc[j][0] * as0 + acc[j][1] * as1;
            d0 += acc[j][0] * ad0 + acc[j][1] * ad1;
            s1 += acc[j][2] * as0 + acc[j][3] * as1;
            d1 += acc[j][2] * ad0 + acc[j][3] * ad1;
            if (r0 < N)
                *(__half2*)&g_xh[(size_t)r0 * F + c0] = __floats2half2_rn(acc[j][0], acc[j][1]);
            if (r1 < N)
                *(__half2*)&g_xh[(size_t)r1 * F + c0] = __floats2half2_rn(acc[j][2], acc[j][3]);
        }
        #pragma unroll
        for (int o = 1; o <= 2; o <<= 1) {
            s0 += __shfl_xor_sync(0xFFFFFFFFu, s0, o);
            d0 += __shfl_xor_sync(0xFFFFFFFFu, d0, o);
            s1 += __shfl_xor_sync(0xFFFFFFFFu, s1, o);
            d1 += __shfl_xor_sync(0xFFFFFFFFu, d1, o);
        }
        if (t == 0) {
            if (r0 < N) { g_asrc[r0] = s0; g_adst[r0] = d0; }
            if (r1 < N) { g_asrc[r1] = s1; g_adst[r1] = d1; }
        }
    }
}

// ---------------- GEMM2: persistent, A fp16 (g_h1h), hi-only, 4 blocks/SM ----------------
// 128 threads (4 warps), BM=64, F=64. D = Ah*(Wh + Wl): 2 MMAs per (kc,j).
__global__ __launch_bounds__(128) void gemm_mma2(const __half* __restrict__ Wth,
                                                 const __half* __restrict__ Wtl,
                                                 const float* __restrict__ atts,
                                                 const float* __restrict__ attd,
                                                 int N, int numTiles) {
    constexpr int F = 64, KP = 136, NT = 8;
    extern __shared__ __align__(16) char smem_raw[];
    __half* sWh = (__half*)smem_raw;              // [F][KP]
    __half* sWl = sWh + F * KP;
    __half* sAh = sWl + F * KP;                   // [64][KP] fp16 (single buffer)

    const int tid = threadIdx.x;
    const int warp = tid >> 5;
    const int lane = tid & 31;
    const int g = lane >> 2, t = lane & 3;
    const int arow = warp * 16;
    const uint32_t sa = (uint32_t)__cvta_generic_to_shared(sAh);

    // stage W once
    {
        uint32_t swh = (uint32_t)__cvta_generic_to_shared(sWh);
        uint32_t swl = (uint32_t)__cvta_generic_to_shared(sWl);
        for (int q = tid; q < F * 16; q += 128) {
            int n = q >> 4, c = q & 15;
            cp_async16(swh + n * (KP * 2) + c * 16, Wth + n * 128 + c * 8);
            cp_async16(swl + n * (KP * 2) + c * 16, Wtl + n * 128 + c * 8);
        }
    }

    bool first = true;
    for (int tile = blockIdx.x; tile < numTiles; tile += gridDim.x) {
        if (!first) __syncthreads();
        // stage A fp16: 64 rows x 16 chunks(16B=8 halves) = 1024 / 128 = 8 each
        {
            int row0 = tile * 64;
            #pragma unroll
            for (int q = 0; q < 8; q++) {
                int f8 = tid + q * 128;
                int r = f8 >> 4, c = f8 & 15;
                int gr = row0 + r;
                if (gr >= N) gr = N - 1;
                cp_async16(sa + (uint32_t)(r * KP + c * 8) * 2, g_h1h + (size_t)gr * 128 + c * 8);
            }
            cp_commit();
        }
        cp_wait0();
        __syncthreads();
        first = false;

        const int row0 = tile * 64;
        float acc[NT][4];
        #pragma unroll
        for (int j = 0; j < NT; j++)
            #pragma unroll
            for (int q = 0; q < 4; q++) acc[j][q] = 0.f;

        #pragma unroll
        for (int kc = 0; kc < 8; kc++) {
            const int kb = kc * 16;
            uint32_t ah[4];
            {
                const __half* pa = sAh + (arow + g) * KP + kb + 2 * t;
                ah[0] = *(const uint32_t*)pa;
                ah[1] = *(const uint32_t*)(pa + 8 * KP);
                ah[2] = *(const uint32_t*)(pa + 8);
                ah[3] = *(const uint32_t*)(pa + 8 * KP + 8);
            }
            #pragma unroll
            for (int j = 0; j < NT; j++) {
                const __half* pb = sWh + (j * 8 + g) * KP + kb + 2 * t;
                uint32_t bh0 = *(const uint32_t*)pb;
                uint32_t bh1 = *(const uint32_t*)(pb + 8);
                const __half* pc = sWl + (j * 8 + g) * KP + kb + 2 * t;
                uint32_t bl0 = *(const uint32_t*)pc;
                uint32_t bl1 = *(const uint32_t*)(pc + 8);
                mma16816(acc[j], ah, bh0, bh1);
                mma16816(acc[j], ah, bl0, bl1);
            }
        }

        // epilogue
        int r0 = row0 + arow + g;
        int r1 = r0 + 8;
        float s0 = 0.f, d0 = 0.f, s1 = 0.f, d1 = 0.f;
        #pragma unroll
        for (int j = 0; j < NT; j++) {
            int c0 = j * 8 + 2 * t;
            float as0 = __ldg(&atts[c0]), as1 = __ldg(&atts[c0 + 1]);
            float ad0 = __ldg(&attd[c0]), ad1 = __ldg(&attd[c0 + 1]);
            s0 += acc[j][0] * as0 + acc[j][1] * as1;
            d0 += acc[j][0] * ad0 + acc[j][1] * ad1;
            s1 += acc[j][2] * as0 + acc[j][3] * as1;
            d1 += acc[j][2] * ad0 + acc[j][3] * ad1;
            if (r0 < N)
                *(__half2*)&g_xh[(size_t)r0 * F + c0] = __floats2half2_rn(acc[j][0], acc[j][1]);
            if (r1 < N)
                *(__half2*)&g_xh[(size_t)r1 * F + c0] = __floats2half2_rn(acc[j][2], acc[j][3]);
        }
        #pragma unroll
        for (int o = 1; o <= 2; o <<= 1) {
            s0 += __shfl_xor_sync(0xFFFFFFFFu, s0, o);
            d0 += __shfl_xor_sync(0xFFFFFFFFu, d0, o);
            s1 += __shfl_xor_sync(0xFFFFFFFFu, s1, o);
            d1 += __shfl_xor_sync(0xFFFFFFFFu, d1, o);
        }
        if (t == 0) {
            if (r0 < N) { g_asrc[r0] = s0; g_adst[r0] = d0; }
            if (r1 < N) { g_asrc[r1] = s1; g_adst[r1] = d1; }
        }
    }
}

// ---------------- feature load helper (fp16 -> fp32) ----------------
template <int VE>
__device__ __forceinline__ void load_feat(float* v, const __half* p) {
    if (VE == 4) {
        uint2 u = *(const uint2*)p;
        float2 f0 = __half22float2(*(const __half2*)&u.x);
        float2 f1 = __half22float2(*(const __half2*)&u.y);
        v[0] = f0.x; v[1] = f0.y; v[2] = f1.x; v[3] = f1.y;
    } else {
        uint32_t u = *(const uint32_t*)p;
        float2 f0 = __half22float2(*(const __half2*)&u);
        v[0] = f0.x; v[1] = f0.y;
    }
}

// ---------------- fused GAT (R12 proven form): self-loop-first online softmax ----------------
// OUT_HALF: layer-1 writes fp16 g_h1h; layer-2 writes fp32 outp.
template <int F, bool OUT_HALF>
__global__ void fused_gat(const float* __restrict__ bias, const float* __restrict__ prelu_a,
                          float* __restrict__ outp, int N, int layer) {
    int w = (blockIdx.x * blockDim.x + threadIdx.x) >> 5;
    int lane = threadIdx.x & 31;
    if (w >= N) return;
    constexpr int VE = F / 32;
    const float c = g_c[layer];
    const float adst = g_adst[w];
    const float lself = leaky(g_asrc[w] + adst + c * g_loopattr[w]);

    float m = lself, den = 1.f;
    float acc[VE];
    load_feat<VE>(acc, g_xh + (size_t)w * F + lane * VE);  // self-loop, p=1 at m=lself

    const int beg = g_rowstart[w] + g_bsum[w >> 8];
    const int cnt = g_cnt[w];

    #define GAT_UPD(lv, vv)                                             \
        if (lv <= m) {                                                  \
            float p = __expf(lv - m);                                   \
            den += p;                                                   \
            _Pragma("unroll")                                           \
            for (int q = 0; q < VE; q++) acc[q] += p * vv[q];           \
        } else {                                                        \
            float sc = __expf(m - lv);                                  \
            den = den * sc + 1.f;                                       \
            _Pragma("unroll")                                           \
            for (int q = 0; q < VE; q++) acc[q] = acc[q] * sc + vv[q];  \
            m = lv;                                                     \
        }

    int j = 0;
    for (; j + 4 <= cnt; j += 4) {
        EdgeRec e0 = g_epack[beg + j];
        EdgeRec e1 = g_epack[beg + j + 1];
        EdgeRec e2 = g_epack[beg + j + 2];
        EdgeRec e3 = g_epack[beg + j + 3];
        float a0 = g_asrc[e0.src], a1 = g_asrc[e1.src];
        float a2 = g_asrc[e2.src], a3 = g_asrc[e3.src];
        float v0[VE], v1[VE], v2[VE], v3[VE];
        load_feat<VE>(v0, g_xh + (size_t)e0.src * F + lane * VE);
        load_feat<VE>(v1, g_xh + (size_t)e1.src * F + lane * VE);
        load_feat<VE>(v2, g_xh + (size_t)e2.src * F + lane * VE);
        load_feat<VE>(v3, g_xh + (size_t)e3.src * F + lane * VE);
        float l0 = leaky(a0 + adst + c * e0.ea);
        float l1 = leaky(a1 + adst + c * e1.ea);
        float l2 = leaky(a2 + adst + c * e2.ea);
        float l3 = leaky(a3 + adst + c * e3.ea);
        GAT_UPD(l0, v0);
        GAT_UPD(l1, v1);
        GAT_UPD(l2, v2);
        GAT_UPD(l3, v3);
    }
    for (; j < cnt; j++) {
        EdgeRec er = g_epack[beg + j];
        float l = leaky(g_asrc[er.src] + adst + c * er.ea);
        float v[VE];
        load_feat<VE>(v, g_xh + (size_t)er.src * F + lane * VE);
        GAT_UPD(l, v);
    }
    #undef GAT_UPD

    float inv = 1.f / den;
    float a = *prelu_a;
    float o[VE];
    #pragma unroll
    for (int q = 0; q < VE; q++) {
        float z = acc[q] * inv + bias[lane * VE + q];
        o[q] = z > 0.f ? z : a * z;
    }
    if (OUT_HALF) {
        __half* dst = g_h1h + (size_t)w * F + lane * VE;
        if (VE == 4) {
            __half2 h0 = __floats2half2_rn(o[0], o[1]);
            __half2 h1 = __floats2half2_rn(o[2], o[3]);
            *(uint2*)dst = make_uint2(*(uint32_t*)&h0, *(uint32_t*)&h1);
        } else {
            __half2 h0 = __floats2half2_rn(o[0], o[1]);
            *(uint32_t*)dst = *(uint32_t*)&h0;
        }
    } else {
        #pragma unroll
        for (int q = 0; q < VE; q++)
            outp[(size_t)w * F + lane * VE + q] = o[q];
    }
}

template <typename T>
static T* sym_addr(const void* sym) {
    void* p = nullptr;
    cudaGetSymbolAddress(&p, sym);
    return (T*)p;
}

extern "C" void kernel_launch(void* const* d_in, const int* in_sizes, int n_in,
                              void* d_out, int out_size) {
    const float*      x    = (const float*)d_in[0];
    const int*        eiw  = (const int*)d_in[1];
    const float*      ea   = (const float*)d_in[2];
    const float*      W1   = (const float*)d_in[3];
    const float*      as1  = (const float*)d_in[4];
    const float*      ad1  = (const float*)d_in[5];
    const float*      We1  = (const float*)d_in[6];
    const float*      ae1  = (const float*)d_in[7];
    const float*      b1   = (const float*)d_in[8];
    const float*      W2   = (const float*)d_in[9];
    const float*      as2  = (const float*)d_in[10];
    const float*      ad2  = (const float*)d_in[11];
    const float*      We2  = (const float*)d_in[12];
    const float*      ae2  = (const float*)d_in[13];
    const float*      b2   = (const float*)d_in[14];
    const float*      pa   = (const float*)d_in[15];
    float*            out  = (float*)d_out;

    const int N = in_sizes[0] / DIN;
    const int E = in_sizes[1] / 2;

    const int TB = 256;
    int nb_N   = (N + TB - 1) / TB;
    int nb_E   = (E + TB - 1) / TB;
    int nb_att = ((N * 32) + TB - 1) / TB;
    int numTiles = (N + 63) / 64;            // BM=64

    const __half* wth1 = sym_addr<__half>(&g_wth1);
    const __half* wtl1 = sym_addr<__half>(&g_wtl1);
    const __half* wth2 = sym_addr<__half>(&g_wth2);
    const __half* wtl2 = sym_addr<__half>(&g_wtl2);

    // gemm1: W hi/lo (128*136*2*2=69632) + A fp32 (64*136*4=34816) = 104448 -> 2 blocks/SM
    // gemm2: W hi/lo (64*136*2*2=34816) + A fp16 (64*136*2=17408) = 52224 -> 4 blocks/SM
    constexpr int SM1 = 2 * H1 * 136 * 2 + 64 * 136 * 4;
    constexpr int SM2 = 2 * H2 * 136 * 2 + 64 * 136 * 2;
    cudaFuncSetAttribute(gemm_mma1, cudaFuncAttributeMaxDynamicSharedMemorySize, SM1);
    cudaFuncSetAttribute(gemm_mma2, cudaFuncAttributeMaxDynamicSharedMemorySize, SM2);
    const int G1 = 296;    // 2 blocks/SM
    const int G2 = 592;    // 4 blocks/SM

    // gemm1 at my-launch #4 (ncu -s 5 profile target)
    prep_misc<<<nb_N + 2 + 96, TB>>>(eiw, We1, ae1, We2, ae2, W1, W2, N, nb_N);  // 1
    conv_hist<<<nb_E, TB>>>(eiw, ea, E, N);                                      // 2
    scan1<<<nb_N, 256>>>(N);                                                     // 3
    gemm_mma1<<<G1, 128, SM1>>>(x, wth1, wtl1, as1, ad1, N, numTiles);           // 4
    scan2<<<1, 1024>>>(nb_N);                                                    // 5
    csr_fill<<<nb_E, TB>>>(eiw, ea, E, N);                                       // 6
    fused_gat<H1, true><<<nb_att, TB>>>(b1, pa, out, N, 0);                      // 7
    gemm_mma2<<<G2, 128, SM2>>>(wth2, wtl2, as2, ad2, N, numTiles);              // 8
    fused_gat<H2, false><<<nb_att, TB>>>(b2, pa, out, N, 1);                     // 9
}